// round 4
// baseline (speedup 1.0000x reference)
#include <cuda_runtime.h>
#include <cstdint>

// ============================================================================
// Fused geometric MLP trunk via mma.sync tf32 (sm_100-plain compatible).
//   rows = 524288, F=13(pad16), H=128, P=64
//   148 persistent CTAs x 128 threads. Weights + activations in SMEM.
//   Each warp owns 32 rows; no CTA-wide sync in the main loop.
// ============================================================================

#define DEVINL static __device__ __forceinline__

// cvt to tf32 needs a .b32 destination register.
DEVINL uint32_t to_tf32u(float x) {
    uint32_t y;
    asm("cvt.rna.tf32.f32 %0, %1;" : "=r"(y) : "f"(x));
    return y;
}
DEVINL float to_tf32(float x) { return __uint_as_float(to_tf32u(x)); }

DEVINL void mma_tf32(float* d, const uint32_t* a, const uint32_t* b) {
    asm volatile(
        "mma.sync.aligned.m16n8k8.row.col.f32.tf32.tf32.f32 "
        "{%0,%1,%2,%3},{%4,%5,%6,%7},{%8,%9},{%0,%1,%2,%3};"
        : "+f"(d[0]), "+f"(d[1]), "+f"(d[2]), "+f"(d[3])
        : "r"(a[0]), "r"(a[1]), "r"(a[2]), "r"(a[3]), "r"(b[0]), "r"(b[1]));
}

// ---------------------------------------------------------------------------
static constexpr int TOTAL_ROWS = 32 * 16384;       // 524288
static constexpr int TILES      = TOTAL_ROWS / 128; // 4096
static constexpr float INV_PI   = 0.3183098861837907f;
static constexpr float INV_2PI  = 0.15915494309189535f;

// SMEM float-index map
static constexpr int PB1 = 0, PG1 = 128, PBT1 = 256;
static constexpr int PB2 = 384, PG2 = 512, PBT2 = 640;
static constexpr int PB3 = 768;
static constexpr int PCRT = 832, PSRT = 848, PRP = 864;
static constexpr int W1F  = 1024;   // blocks [kt2][nt16] * 64 floats = 2048
static constexpr int W2F  = 3072;   // [kt16][nt16] * 64 = 16384
static constexpr int W3F  = 19456;  // [kt16][nt8]  * 64 = 8192
static constexpr int FEATF = 27648; // 128 rows * 32 floats (swizzled)
static constexpr int HF    = 31744; // 128 rows * 128 floats (swizzled)
static constexpr int SMEM_FLOATS = 48128;
static constexpr int SMEM_BYTES  = SMEM_FLOATS * 4; // 192512

// Swizzled activation tile addressing: row stride S floats, 4-float chunks
// permuted by (row & 7) to kill bank conflicts on mma A-fragment reads.
DEVINL int act_idx(int S, int r, int k) {
    return r * S + ((((k >> 2) ^ (r & 7)) << 2) | (k & 3));
}

// Weight fragment-pack: block(kt,nt) is 8x8, stored as 32 lanes x {B[k][n], B[k+4][n]}
// so lane l = (n<<2)|(k&3) reads its whole b-fragment with ONE LDS.64 at l*8.
DEVINL void store_wfrag(float* sf, int off, int NT, int k, int n, float v) {
    int kt = k >> 3, nt = n >> 3, kk = k & 7, nn = n & 7;
    int lane = (nn << 2) | (kk & 3);
    int slot = kk >> 2;
    sf[off + ((kt * NT + nt) * 32 + lane) * 2 + slot] = to_tf32(v);
}

__global__ void __launch_bounds__(128, 1)
geo_trunk_kernel(const float* __restrict__ coords,
                 const float* __restrict__ ref_theta, const float* __restrict__ ref_phi,
                 const float* __restrict__ W1, const float* __restrict__ b1,
                 const float* __restrict__ g1, const float* __restrict__ bt1,
                 const float* __restrict__ W2, const float* __restrict__ b2,
                 const float* __restrict__ g2, const float* __restrict__ bt2,
                 const float* __restrict__ W3, const float* __restrict__ b3,
                 float* __restrict__ out) {
    extern __shared__ float sf[];
    const int tid  = threadIdx.x;
    const int lane = tid & 31;
    const int gid  = lane >> 2;   // row group within fragment
    const int tig  = lane & 3;    // thread-in-group
    const int wrow = (tid >> 5) * 32;  // CTA-local row base of this warp

    // ---- one-time setup ----
    for (int t = tid; t < 2048; t += 128) {           // W1 (zero-pad k>=13)
        int k = t >> 7, n = t & 127;
        store_wfrag(sf, W1F, 16, k, n, k < 13 ? W1[k * 128 + n] : 0.0f);
    }
    for (int t = tid; t < 16384; t += 128) {          // W2
        int k = t >> 7, n = t & 127;
        store_wfrag(sf, W2F, 16, k, n, W2[t]);
    }
    for (int t = tid; t < 8192; t += 128) {           // W3
        int k = t >> 6, n = t & 63;
        store_wfrag(sf, W3F, 8, k, n, W3[t]);
    }
    sf[PB1 + tid]  = b1[tid];
    sf[PG1 + tid]  = g1[tid];
    sf[PBT1 + tid] = bt1[tid];
    sf[PB2 + tid]  = b2[tid];
    sf[PG2 + tid]  = g2[tid];
    sf[PBT2 + tid] = bt2[tid];
    if (tid < 64) sf[PB3 + tid] = b3[tid];
    if (tid < 10) {
        float rt = ref_theta[tid];
        sf[PCRT + tid] = cosf(rt);
        sf[PSRT + tid] = sinf(rt);
        sf[PRP + tid]  = ref_phi[tid];
    }
    __syncthreads();

    const float* bS1 = sf + PB1; const float* gS1 = sf + PG1; const float* tS1 = sf + PBT1;
    const float* bS2 = sf + PB2; const float* gS2 = sf + PG2; const float* tS2 = sf + PBT2;
    const float* bS3 = sf + PB3;
    const float* crt = sf + PCRT; const float* srt = sf + PSRT; const float* rp = sf + PRP;

    for (int tile = blockIdx.x; tile < TILES; tile += gridDim.x) {
        // ================= features (1 row / thread) =================
        {
            const int row = tile * 128 + tid;
            float2 tp = reinterpret_cast<const float2*>(coords)[row];
            float th = tp.x, ph = tp.y;
            float st, ct;
            __sincosf(th, &st, &ct);
            float f[16];
#pragma unroll
            for (int r = 0; r < 10; r++) {
                float cd = fmaf(st * srt[r], __cosf(ph - rp[r]), ct * crt[r]);
                cd = fminf(1.0f, fmaxf(-1.0f, cd));
                f[r] = to_tf32(acosf(cd) * INV_PI);
            }
            f[10] = to_tf32(th * INV_PI);
            f[11] = to_tf32(ph * INV_2PI);
            f[12] = 1.0f;
            f[13] = 0.f; f[14] = 0.f; f[15] = 0.f;
            float4* fr = reinterpret_cast<float4*>(sf + FEATF) + tid * 8;
            int rx = tid & 7;
#pragma unroll
            for (int c = 0; c < 4; c++)
                fr[c ^ rx] = make_float4(f[4 * c], f[4 * c + 1], f[4 * c + 2], f[4 * c + 3]);
        }
        __syncwarp();

        float acc[2][16][4];

        // ================= layer 1: feats[128x16] @ W1 =================
#pragma unroll
        for (int mt = 0; mt < 2; mt++)
#pragma unroll
            for (int nt = 0; nt < 16; nt++)
#pragma unroll
                for (int e = 0; e < 4; e++) acc[mt][nt][e] = 0.f;
#pragma unroll
        for (int kt = 0; kt < 2; kt++) {
            uint32_t a[2][4];
#pragma unroll
            for (int mt = 0; mt < 2; mt++) {
                int rb = wrow + mt * 16;
                a[mt][0] = __float_as_uint(sf[FEATF + act_idx(32, rb + gid,     kt * 8 + tig)]);
                a[mt][1] = __float_as_uint(sf[FEATF + act_idx(32, rb + gid + 8, kt * 8 + tig)]);
                a[mt][2] = __float_as_uint(sf[FEATF + act_idx(32, rb + gid,     kt * 8 + tig + 4)]);
                a[mt][3] = __float_as_uint(sf[FEATF + act_idx(32, rb + gid + 8, kt * 8 + tig + 4)]);
            }
#pragma unroll
            for (int nt = 0; nt < 16; nt++) {
                float2 bv = *reinterpret_cast<const float2*>(sf + W1F + ((kt * 16 + nt) * 32 + lane) * 2);
                uint32_t b[2] = {__float_as_uint(bv.x), __float_as_uint(bv.y)};
                mma_tf32(acc[0][nt], a[0], b);
                mma_tf32(acc[1][nt], a[1], b);
            }
        }

        // ---- LN + ReLU epilogue -> h tile ----
#pragma unroll
        for (int L = 0; L < 2; L++) {  // L=0: layer1 epi + layer2 mma; L=1: layer2 epi
            const float* bS = (L == 0) ? bS1 : bS2;
            const float* gS = (L == 0) ? gS1 : gS2;
            const float* tS = (L == 0) ? tS1 : tS2;
#pragma unroll
            for (int mt = 0; mt < 2; mt++) {
                float s0 = 0.f, s1 = 0.f, q0 = 0.f, q1 = 0.f;
#pragma unroll
                for (int nt = 0; nt < 16; nt++) {
                    int c0 = 8 * nt + 2 * tig;
                    float x0 = acc[mt][nt][0] + bS[c0];
                    float x1 = acc[mt][nt][1] + bS[c0 + 1];
                    float x2 = acc[mt][nt][2] + bS[c0];
                    float x3 = acc[mt][nt][3] + bS[c0 + 1];
                    acc[mt][nt][0] = x0; acc[mt][nt][1] = x1;
                    acc[mt][nt][2] = x2; acc[mt][nt][3] = x3;
                    s0 += x0 + x1; q0 += x0 * x0 + x1 * x1;
                    s1 += x2 + x3; q1 += x2 * x2 + x3 * x3;
                }
                s0 += __shfl_xor_sync(0xffffffffu, s0, 1);
                s0 += __shfl_xor_sync(0xffffffffu, s0, 2);
                q0 += __shfl_xor_sync(0xffffffffu, q0, 1);
                q0 += __shfl_xor_sync(0xffffffffu, q0, 2);
                s1 += __shfl_xor_sync(0xffffffffu, s1, 1);
                s1 += __shfl_xor_sync(0xffffffffu, s1, 2);
                q1 += __shfl_xor_sync(0xffffffffu, q1, 1);
                q1 += __shfl_xor_sync(0xffffffffu, q1, 2);
                float mu0 = s0 * 0.0078125f;
                float mu1 = s1 * 0.0078125f;
                float rs0 = rsqrtf(fmaf(-mu0, mu0, q0 * 0.0078125f) + 1e-5f);
                float rs1 = rsqrtf(fmaf(-mu1, mu1, q1 * 0.0078125f) + 1e-5f);
                int r0 = wrow + mt * 16 + gid, r1 = r0 + 8;
#pragma unroll
                for (int nt = 0; nt < 16; nt++) {
                    int c0 = 8 * nt + 2 * tig;
                    float2 y0, y1;
                    y0.x = to_tf32(fmaxf(fmaf((acc[mt][nt][0] - mu0) * rs0, gS[c0],     tS[c0]),     0.f));
                    y0.y = to_tf32(fmaxf(fmaf((acc[mt][nt][1] - mu0) * rs0, gS[c0 + 1], tS[c0 + 1]), 0.f));
                    y1.x = to_tf32(fmaxf(fmaf((acc[mt][nt][2] - mu1) * rs1, gS[c0],     tS[c0]),     0.f));
                    y1.y = to_tf32(fmaxf(fmaf((acc[mt][nt][3] - mu1) * rs1, gS[c0 + 1], tS[c0 + 1]), 0.f));
                    *reinterpret_cast<float2*>(sf + HF + act_idx(128, r0, c0)) = y0;
                    *reinterpret_cast<float2*>(sf + HF + act_idx(128, r1, c0)) = y1;
                }
            }
            __syncwarp();

            if (L == 1) break;

            // ================= layer 2: h1[128x128] @ W2 =================
#pragma unroll
            for (int mt = 0; mt < 2; mt++)
#pragma unroll
                for (int nt = 0; nt < 16; nt++)
#pragma unroll
                    for (int e = 0; e < 4; e++) acc[mt][nt][e] = 0.f;
#pragma unroll
            for (int kt = 0; kt < 16; kt++) {
                uint32_t a[2][4];
#pragma unroll
                for (int mt = 0; mt < 2; mt++) {
                    int rb = wrow + mt * 16;
                    a[mt][0] = __float_as_uint(sf[HF + act_idx(128, rb + gid,     kt * 8 + tig)]);
                    a[mt][1] = __float_as_uint(sf[HF + act_idx(128, rb + gid + 8, kt * 8 + tig)]);
                    a[mt][2] = __float_as_uint(sf[HF + act_idx(128, rb + gid,     kt * 8 + tig + 4)]);
                    a[mt][3] = __float_as_uint(sf[HF + act_idx(128, rb + gid + 8, kt * 8 + tig + 4)]);
                }
#pragma unroll
                for (int nt = 0; nt < 16; nt++) {
                    float2 bv = *reinterpret_cast<const float2*>(sf + W2F + ((kt * 16 + nt) * 32 + lane) * 2);
                    uint32_t b[2] = {__float_as_uint(bv.x), __float_as_uint(bv.y)};
                    mma_tf32(acc[0][nt], a[0], b);
                    mma_tf32(acc[1][nt], a[1], b);
                }
            }
        }

        // ================= layer 3: h2[128x128] @ W3 + b3 -> out =================
        float a3[2][8][4];
#pragma unroll
        for (int mt = 0; mt < 2; mt++)
#pragma unroll
            for (int nt = 0; nt < 8; nt++)
#pragma unroll
                for (int e = 0; e < 4; e++) a3[mt][nt][e] = 0.f;
#pragma unroll
        for (int kt = 0; kt < 16; kt++) {
            uint32_t a[2][4];
#pragma unroll
            for (int mt = 0; mt < 2; mt++) {
                int rb = wrow + mt * 16;
                a[mt][0] = __float_as_uint(sf[HF + act_idx(128, rb + gid,     kt * 8 + tig)]);
                a[mt][1] = __float_as_uint(sf[HF + act_idx(128, rb + gid + 8, kt * 8 + tig)]);
                a[mt][2] = __float_as_uint(sf[HF + act_idx(128, rb + gid,     kt * 8 + tig + 4)]);
                a[mt][3] = __float_as_uint(sf[HF + act_idx(128, rb + gid + 8, kt * 8 + tig + 4)]);
            }
#pragma unroll
            for (int nt = 0; nt < 8; nt++) {
                float2 bv = *reinterpret_cast<const float2*>(sf + W3F + ((kt * 8 + nt) * 32 + lane) * 2);
                uint32_t b[2] = {__float_as_uint(bv.x), __float_as_uint(bv.y)};
                mma_tf32(a3[0][nt], a[0], b);
                mma_tf32(a3[1][nt], a[1], b);
            }
        }
        {
            const int rowg0 = tile * 128 + wrow;
#pragma unroll
            for (int mt = 0; mt < 2; mt++) {
                int r0 = rowg0 + mt * 16 + gid, r1 = r0 + 8;
#pragma unroll
                for (int nt = 0; nt < 8; nt++) {
                    int c0 = 8 * nt + 2 * tig;
                    float2 v0 = make_float2(a3[mt][nt][0] + bS3[c0], a3[mt][nt][1] + bS3[c0 + 1]);
                    float2 v1 = make_float2(a3[mt][nt][2] + bS3[c0], a3[mt][nt][3] + bS3[c0 + 1]);
                    *reinterpret_cast<float2*>(out + (size_t)r0 * 64 + c0) = v0;
                    *reinterpret_cast<float2*>(out + (size_t)r1 * 64 + c0) = v1;
                }
            }
        }
        // next tile's L1-epilogue writes to h happen after a __syncwarp in the
        // feature stage, so the L3 reads above are safely ordered.
    }
}

extern "C" void kernel_launch(void* const* d_in, const int* in_sizes, int n_in,
                              void* d_out, int out_size) {
    (void)in_sizes; (void)n_in; (void)out_size;
    cudaFuncSetAttribute(geo_trunk_kernel, cudaFuncAttributeMaxDynamicSharedMemorySize, SMEM_BYTES);
    geo_trunk_kernel<<<148, 128, SMEM_BYTES>>>(
        (const float*)d_in[0],  // coords
        (const float*)d_in[1],  // ref_theta
        (const float*)d_in[2],  // ref_phi
        (const float*)d_in[3],  // W1
        (const float*)d_in[4],  // b1
        (const float*)d_in[5],  // g1
        (const float*)d_in[6],  // bt1
        (const float*)d_in[7],  // W2
        (const float*)d_in[8],  // b2
        (const float*)d_in[9],  // g2
        (const float*)d_in[10], // bt2
        (const float*)d_in[11], // W3
        (const float*)d_in[12], // b3
        (float*)d_out);
}

// round 5
// speedup vs baseline: 2.5092x; 2.5092x over previous
#include <cuda_runtime.h>
#include <cuda_fp16.h>
#include <cstdint>

// ============================================================================
// Fused geometric MLP trunk, fp16 mma.sync m16n8k16 (sm_100-plain).
//   rows = 524288, F=13(pad16), H=128, P=64
//   148 persistent CTAs x 256 threads (8 warps), 256-row tiles.
//   Weights fp16 fragment-packed in SMEM (~52KB). Activations NEVER touch
//   smem after layer 1: the f16 A-fragment of layer L+1 is lane-local in the
//   C-fragment of layer L (cols 16kt+2tig <-> C blocks nt=2kt,2kt+1).
// ============================================================================

#define DEVINL static __device__ __forceinline__

DEVINL void mma_f16(float* d, const uint32_t* a, const uint32_t* b) {
    asm volatile(
        "mma.sync.aligned.m16n8k16.row.col.f32.f16.f16.f32 "
        "{%0,%1,%2,%3},{%4,%5,%6,%7},{%8,%9},{%0,%1,%2,%3};"
        : "+f"(d[0]), "+f"(d[1]), "+f"(d[2]), "+f"(d[3])
        : "r"(a[0]), "r"(a[1]), "r"(a[2]), "r"(a[3]), "r"(b[0]), "r"(b[1]));
}

// ---------------------------------------------------------------------------
static constexpr int TOTAL_ROWS = 32 * 16384;       // 524288
static constexpr int TILE_ROWS  = 256;
static constexpr int TILES      = TOTAL_ROWS / TILE_ROWS;  // 2048
static constexpr float INV_PI   = 0.3183098861837907f;
static constexpr float INV_2PI  = 0.15915494309189535f;

// SMEM word (uint32) map
static constexpr int PB1 = 0, PG1 = 128, PBT1 = 256;
static constexpr int PB2 = 384, PG2 = 512, PBT2 = 640;
static constexpr int PB3 = 768;                 // 64
static constexpr int PCRT = 832, PSRT = 848, PRP = 864;
static constexpr int W1F = 896;                 // 16 blocks * 64 words = 1024
static constexpr int W2F = 1920;                // 128 blocks * 64 = 8192
static constexpr int W3F = 10112;               // 64 blocks * 64 = 4096
static constexpr int F2  = 14208;               // 256 rows * 8 half2-words = 2048
static constexpr int SMEM_WORDS = 16256;
static constexpr int SMEM_BYTES = SMEM_WORDS * 4;  // 65024

// Weight fragment packing for m16n8k16 f16, B col-major K x N:
// block (kt, nt) covers k in [16kt,16kt+16), n in [8nt, 8nt+8).
// lane l = (n&7)*4 + tig holds b0 = {B[16kt+2tig][n], B[16kt+2tig+1][n]},
//                            b1 = {B[16kt+2tig+8][n], B[16kt+2tig+9][n]}.
DEVINL void pack_w(__half* hw, int base_words, int block, int kk, int nn, float v) {
    int lane = (nn << 2) | ((kk >> 1) & 3);
    int s    = kk >> 3;
    int pos  = kk & 1;
    hw[(base_words + block * 64 + lane * 2 + s) * 2 + pos] = __float2half_rn(v);
}

__global__ void __launch_bounds__(256, 1)
geo_trunk_kernel(const float* __restrict__ coords,
                 const float* __restrict__ ref_theta, const float* __restrict__ ref_phi,
                 const float* __restrict__ W1, const float* __restrict__ b1,
                 const float* __restrict__ g1, const float* __restrict__ bt1,
                 const float* __restrict__ W2, const float* __restrict__ b2,
                 const float* __restrict__ g2, const float* __restrict__ bt2,
                 const float* __restrict__ W3, const float* __restrict__ b3,
                 float* __restrict__ out) {
    extern __shared__ float sf[];
    uint32_t* su = reinterpret_cast<uint32_t*>(sf);
    __half*   hw = reinterpret_cast<__half*>(sf);

    const int tid  = threadIdx.x;
    const int lane = tid & 31;
    const int gid  = lane >> 2;
    const int tig  = lane & 3;
    const int wrow = (tid >> 5) * 32;   // CTA-local row base of this warp

    // ---- one-time setup: pack weights fp16, params fp32 ----
    for (int t = tid; t < 16 * 128; t += 256) {        // W1 (zero-pad k>=13)
        int k = t >> 7, n = t & 127;
        pack_w(hw, W1F, n >> 3, k & 15, n & 7, k < 13 ? W1[k * 128 + n] : 0.0f);
    }
    for (int t = tid; t < 128 * 128; t += 256) {       // W2
        int k = t >> 7, n = t & 127;
        pack_w(hw, W2F, (k >> 4) * 16 + (n >> 3), k & 15, n & 7, W2[t]);
    }
    for (int t = tid; t < 128 * 64; t += 256) {        // W3
        int k = t >> 6, n = t & 63;
        pack_w(hw, W3F, (k >> 4) * 8 + (n >> 3), k & 15, n & 7, W3[t]);
    }
    if (tid < 128) {
        sf[PB1 + tid]  = b1[tid];
        sf[PG1 + tid]  = g1[tid];
        sf[PBT1 + tid] = bt1[tid];
        sf[PB2 + tid]  = b2[tid];
        sf[PG2 + tid]  = g2[tid];
        sf[PBT2 + tid] = bt2[tid];
        if (tid < 64) sf[PB3 + tid] = b3[tid];
        if (tid < 10) {
            float rt = ref_theta[tid];
            sf[PCRT + tid] = cosf(rt);
            sf[PSRT + tid] = sinf(rt);
            sf[PRP + tid]  = ref_phi[tid];
        }
    }
    __syncthreads();

    const float* bS1 = sf + PB1; const float* gS1 = sf + PG1; const float* tS1 = sf + PBT1;
    const float* bS2 = sf + PB2; const float* gS2 = sf + PG2; const float* tS2 = sf + PBT2;
    const float* bS3 = sf + PB3;
    const float* crt = sf + PCRT; const float* srt = sf + PSRT; const float* rp = sf + PRP;

    for (int tile = blockIdx.x; tile < TILES; tile += gridDim.x) {
        // ============== features: 1 row / thread, store half2 to F2 ==============
        {
            const int row = tile * TILE_ROWS + tid;
            float2 tp = reinterpret_cast<const float2*>(coords)[row];
            float th = tp.x, ph = tp.y;
            float st, ct;
            __sincosf(th, &st, &ct);
            float f[16];
#pragma unroll
            for (int r = 0; r < 10; r++) {
                float cd = fmaf(st * srt[r], __cosf(ph - rp[r]), ct * crt[r]);
                cd = fminf(1.0f, fmaxf(-1.0f, cd));
                f[r] = acosf(cd) * INV_PI;
            }
            f[10] = th * INV_PI;
            f[11] = ph * INV_2PI;
            f[12] = 1.0f;
            f[13] = 0.f; f[14] = 0.f; f[15] = 0.f;
            const int sw = ((tid >> 2) & 1) << 2;  // feat swizzle bit
#pragma unroll
            for (int i = 0; i < 8; i++) {
                __half2 h = __floats2half2_rn(f[2 * i], f[2 * i + 1]);
                su[F2 + tid * 8 + (i ^ sw)] = *reinterpret_cast<uint32_t*>(&h);
            }
        }
        __syncwarp();

        float    acc[2][16][4];
        uint32_t ha[2][8][4];   // activation A-fragments (half2), layer L -> L+1

        // ============== layer 1: feats[256x16] @ W1 (1 k-step) ==============
#pragma unroll
        for (int mt = 0; mt < 2; mt++)
#pragma unroll
            for (int nt = 0; nt < 16; nt++)
#pragma unroll
                for (int e = 0; e < 4; e++) acc[mt][nt][e] = 0.f;
        {
            uint32_t a[2][4];
#pragma unroll
            for (int mt = 0; mt < 2; mt++) {
                int r0 = wrow + mt * 16 + gid;            // r1 = r0+8 shares swizzle bit
                int s0 = ((r0 >> 2) & 1) << 2;
                a[mt][0] = su[F2 + r0 * 8       + (tig ^ s0)];
                a[mt][1] = su[F2 + (r0 + 8) * 8 + (tig ^ s0)];
                a[mt][2] = su[F2 + r0 * 8       + ((tig + 4) ^ s0)];
                a[mt][3] = su[F2 + (r0 + 8) * 8 + ((tig + 4) ^ s0)];
            }
#pragma unroll
            for (int nt = 0; nt < 16; nt++) {
                uint2 bv = *reinterpret_cast<const uint2*>(su + W1F + nt * 64 + lane * 2);
                uint32_t b[2] = {bv.x, bv.y};
                mma_f16(acc[0][nt], a[0], b);
                mma_f16(acc[1][nt], a[1], b);
            }
        }

        // ============== LN+ReLU epilogues + GEMMs 2,3 ==============
#pragma unroll
        for (int L = 0; L < 2; L++) {
            const float* bS = (L == 0) ? bS1 : bS2;
            const float* gS = (L == 0) ? gS1 : gS2;
            const float* tS = (L == 0) ? tS1 : tS2;
#pragma unroll
            for (int mt = 0; mt < 2; mt++) {
                float s0 = 0.f, s1 = 0.f, q0 = 0.f, q1 = 0.f;
#pragma unroll
                for (int nt = 0; nt < 16; nt++) {
                    int c0 = 8 * nt + 2 * tig;
                    float x0 = acc[mt][nt][0] + bS[c0];
                    float x1 = acc[mt][nt][1] + bS[c0 + 1];
                    float x2 = acc[mt][nt][2] + bS[c0];
                    float x3 = acc[mt][nt][3] + bS[c0 + 1];
                    acc[mt][nt][0] = x0; acc[mt][nt][1] = x1;
                    acc[mt][nt][2] = x2; acc[mt][nt][3] = x3;
                    s0 += x0 + x1; q0 += x0 * x0 + x1 * x1;
                    s1 += x2 + x3; q1 += x2 * x2 + x3 * x3;
                }
                s0 += __shfl_xor_sync(0xffffffffu, s0, 1);
                s0 += __shfl_xor_sync(0xffffffffu, s0, 2);
                q0 += __shfl_xor_sync(0xffffffffu, q0, 1);
                q0 += __shfl_xor_sync(0xffffffffu, q0, 2);
                s1 += __shfl_xor_sync(0xffffffffu, s1, 1);
                s1 += __shfl_xor_sync(0xffffffffu, s1, 2);
                q1 += __shfl_xor_sync(0xffffffffu, q1, 1);
                q1 += __shfl_xor_sync(0xffffffffu, q1, 2);
                float mu0 = s0 * 0.0078125f;
                float mu1 = s1 * 0.0078125f;
                float rs0 = rsqrtf(fmaf(-mu0, mu0, q0 * 0.0078125f) + 1e-5f);
                float rs1 = rsqrtf(fmaf(-mu1, mu1, q1 * 0.0078125f) + 1e-5f);
                // pack normalized activations straight into A-fragments:
                // A block kt <-> C blocks nt = 2kt (k-low) and 2kt+1 (k-high)
#pragma unroll
                for (int kt = 0; kt < 8; kt++) {
                    int cA = 16 * kt + 2 * tig;
                    int cB = cA + 8;
                    float y00 = fmaxf(fmaf((acc[mt][2*kt][0]   - mu0) * rs0, gS[cA],     tS[cA]),     0.f);
                    float y01 = fmaxf(fmaf((acc[mt][2*kt][1]   - mu0) * rs0, gS[cA + 1], tS[cA + 1]), 0.f);
                    float y10 = fmaxf(fmaf((acc[mt][2*kt][2]   - mu1) * rs1, gS[cA],     tS[cA]),     0.f);
                    float y11 = fmaxf(fmaf((acc[mt][2*kt][3]   - mu1) * rs1, gS[cA + 1], tS[cA + 1]), 0.f);
                    float z00 = fmaxf(fmaf((acc[mt][2*kt+1][0] - mu0) * rs0, gS[cB],     tS[cB]),     0.f);
                    float z01 = fmaxf(fmaf((acc[mt][2*kt+1][1] - mu0) * rs0, gS[cB + 1], tS[cB + 1]), 0.f);
                    float z10 = fmaxf(fmaf((acc[mt][2*kt+1][2] - mu1) * rs1, gS[cB],     tS[cB]),     0.f);
                    float z11 = fmaxf(fmaf((acc[mt][2*kt+1][3] - mu1) * rs1, gS[cB + 1], tS[cB + 1]), 0.f);
                    __half2 h;
                    h = __floats2half2_rn(y00, y01); ha[mt][kt][0] = *reinterpret_cast<uint32_t*>(&h);
                    h = __floats2half2_rn(y10, y11); ha[mt][kt][1] = *reinterpret_cast<uint32_t*>(&h);
                    h = __floats2half2_rn(z00, z01); ha[mt][kt][2] = *reinterpret_cast<uint32_t*>(&h);
                    h = __floats2half2_rn(z10, z11); ha[mt][kt][3] = *reinterpret_cast<uint32_t*>(&h);
                }
            }

            if (L == 1) break;

            // ============== layer 2: h1 @ W2 (8 k-steps) ==============
#pragma unroll
            for (int mt = 0; mt < 2; mt++)
#pragma unroll
                for (int nt = 0; nt < 16; nt++)
#pragma unroll
                    for (int e = 0; e < 4; e++) acc[mt][nt][e] = 0.f;
#pragma unroll
            for (int kt = 0; kt < 8; kt++) {
#pragma unroll
                for (int nt = 0; nt < 16; nt++) {
                    uint2 bv = *reinterpret_cast<const uint2*>(su + W2F + (kt * 16 + nt) * 64 + lane * 2);
                    uint32_t b[2] = {bv.x, bv.y};
                    mma_f16(acc[0][nt], ha[0][kt], b);
                    mma_f16(acc[1][nt], ha[1][kt], b);
                }
            }
        }

        // ============== layer 3: h2 @ W3 + b3 -> out ==============
        float a3[2][8][4];
#pragma unroll
        for (int mt = 0; mt < 2; mt++)
#pragma unroll
            for (int nt = 0; nt < 8; nt++)
#pragma unroll
                for (int e = 0; e < 4; e++) a3[mt][nt][e] = 0.f;
#pragma unroll
        for (int kt = 0; kt < 8; kt++) {
#pragma unroll
            for (int nt = 0; nt < 8; nt++) {
                uint2 bv = *reinterpret_cast<const uint2*>(su + W3F + (kt * 8 + nt) * 64 + lane * 2);
                uint32_t b[2] = {bv.x, bv.y};
                mma_f16(a3[0][nt], ha[0][kt], b);
                mma_f16(a3[1][nt], ha[1][kt], b);
            }
        }
        {
            const int rowg = tile * TILE_ROWS + wrow;
#pragma unroll
            for (int mt = 0; mt < 2; mt++) {
                int r0 = rowg + mt * 16 + gid, r1 = r0 + 8;
#pragma unroll
                for (int nt = 0; nt < 8; nt++) {
                    int c0 = 8 * nt + 2 * tig;
                    float2 v0 = make_float2(a3[mt][nt][0] + bS3[c0], a3[mt][nt][1] + bS3[c0 + 1]);
                    float2 v1 = make_float2(a3[mt][nt][2] + bS3[c0], a3[mt][nt][3] + bS3[c0 + 1]);
                    *reinterpret_cast<float2*>(out + (size_t)r0 * 64 + c0) = v0;
                    *reinterpret_cast<float2*>(out + (size_t)r1 * 64 + c0) = v1;
                }
            }
        }
    }
}

extern "C" void kernel_launch(void* const* d_in, const int* in_sizes, int n_in,
                              void* d_out, int out_size) {
    (void)in_sizes; (void)n_in; (void)out_size;
    cudaFuncSetAttribute(geo_trunk_kernel, cudaFuncAttributeMaxDynamicSharedMemorySize, SMEM_BYTES);
    geo_trunk_kernel<<<148, 256, SMEM_BYTES>>>(
        (const float*)d_in[0],  // coords
        (const float*)d_in[1],  // ref_theta
        (const float*)d_in[2],  // ref_phi
        (const float*)d_in[3],  // W1
        (const float*)d_in[4],  // b1
        (const float*)d_in[5],  // g1
        (const float*)d_in[6],  // bt1
        (const float*)d_in[7],  // W2
        (const float*)d_in[8],  // b2
        (const float*)d_in[9],  // g2
        (const float*)d_in[10], // bt2
        (const float*)d_in[11], // W3
        (const float*)d_in[12], // b3
        (float*)d_out);
}